// round 15
// baseline (speedup 1.0000x reference)
#include <cuda_runtime.h>
#include <cuda_bf16.h>

// VolumeSDF renderer: one warp per ray, 4 samples per lane,
// base-2 exponentials with pre-folded constants. (R11/R13 structure; R12
// proved dur tracks BYTES at ~constant 5.5 TB/s achieved BW.)
//
//   density = ALPHA * LaplaceCDF(-sdf; BETA)
//   tau_s   = density_s * delta_s,  delta = diff(depth), last = 1e10
//   T_s     = exp(-inclusive_cumsum(tau)_s);  w_s = T_s*(1-exp(-tau_s+eps))
//   out[n]  = sum_s w_s * color[n,s,:]
//
// Byte savings: tail weight past prefix p telescopes to <= 2^-p, so lanes
// >=16 with prefix >= SKIP2 skip their color loads. Threshold 7.0 nats.
// Calibrated error curve (R11: 9 nats -> 6.0e-5, R13: 8 nats -> 1.28e-4,
// x2.1/nat): predicted rel_err ~2.7e-4, 4x under the 1e-3 gate.
// Lanes 0-15 load color unconditionally, front-batched with sdf/depth.

#define FAR_DELTA 1e10f
#define AEXP   28.853900817779268f   // (1/BETA)*log2(e) = 20*1.442695
#define DENS2  14.426950408889634f   // ALPHA*log2(e)
#define EPS2   1.442695041e-10f      // EPS*log2(e)
#define SKIP2  10.098865286222745f   // 7.0 nats in bits; 2^-10.10 = 9.1e-4
#define EARLY_LANES 16

__device__ __forceinline__ float ex2(float x) {
    float y;
    asm("ex2.approx.ftz.f32 %0, %1;" : "=f"(y) : "f"(x));
    return y;
}

// tau per unit delta, in base-2 units: DENS2 * LaplaceCDF(-x, BETA)
__device__ __forceinline__ float dens2(float x) {
    const float e = 0.5f * ex2(-fabsf(x) * AEXP);
    const float cdf = (x > 0.0f) ? e : (1.0f - e);
    return DENS2 * cdf;
}

__global__ __launch_bounds__(256)
void volume_sdf_render_kernel(const float* __restrict__ sdf,
                              const float* __restrict__ color,
                              const float* __restrict__ depth,
                              float* __restrict__ out,
                              int N)
{
    const int gtid = blockIdx.x * blockDim.x + threadIdx.x;
    const int ray  = gtid >> 5;          // one warp per ray
    const int lane = threadIdx.x & 31;
    if (ray >= N) return;

    const int S = 128;
    const long long base  = (long long)ray * S + lane * 4;
    const long long cbase = base * 3;
    const bool early = (lane < EARLY_LANES);

    // ---- Front-batched loads: sdf, depth (+ color for lanes 0-15) ----
    const float4 s4 = *reinterpret_cast<const float4*>(sdf   + base);
    const float4 d4 = *reinterpret_cast<const float4*>(depth + base);
    float4 ca, cb, cc;
    if (early) {
        ca = *reinterpret_cast<const float4*>(color + cbase);
        cb = *reinterpret_cast<const float4*>(color + cbase + 4);
        cc = *reinterpret_cast<const float4*>(color + cbase + 8);
    }

    // Deltas. depth[4l+4] lives in the next lane's d4.x.
    const float dnext = __shfl_down_sync(0xffffffffu, d4.x, 1);
    float del[4];
    del[0] = d4.y - d4.x;
    del[1] = d4.z - d4.y;
    del[2] = d4.w - d4.z;
    del[3] = (lane == 31) ? FAR_DELTA : (dnext - d4.w);

    const float sd[4] = {s4.x, s4.y, s4.z, s4.w};

    // tau in base-2 units; u_i = 2^(-tau2_i + eps2) = 1 - trans_i.
    float tau[4], u[4];
#pragma unroll
    for (int i = 0; i < 4; ++i) {
        tau[i] = dens2(sd[i]) * del[i];
        u[i]   = ex2(-tau[i] + EPS2);
    }

    // Per-lane inclusive cumsum (base-2 units).
    const float c0 = tau[0];
    const float c1 = c0 + tau[1];
    const float c2 = c1 + tau[2];
    const float c3 = c2 + tau[3];

    // Warp inclusive scan of lane totals.
    float incl = c3;
#pragma unroll
    for (int off = 1; off < 32; off <<= 1) {
        const float v = __shfl_up_sync(0xffffffffu, incl, off);
        if (lane >= off) incl += v;
    }
    // Exclusive prefix from the PREVIOUS lane's inclusive value. Never by
    // subtraction: lane 31's c3 holds the far-delta tau and the subtraction
    // catastrophically cancels (R1/R2 rel_err=0.33 bug).
    float prefix = __shfl_up_sync(0xffffffffu, incl, 1);
    if (lane == 0) prefix = 0.0f;

    // Gated lanes: load color only if tail bound 2^-prefix is significant.
    const bool have = early || (prefix < SKIP2);
    if (!early && have) {
        ca = *reinterpret_cast<const float4*>(color + cbase);
        cb = *reinterpret_cast<const float4*>(color + cbase + 4);
        cc = *reinterpret_cast<const float4*>(color + cbase + 8);
    }

    float r = 0.0f, g = 0.0f, b = 0.0f;
    if (have) {
        // Telescoping transmittance: T0 = 2^-(prefix+c0); T_{i+1} = T_i*u_{i+1}
        // (eps factor in u is ~1+1e-10, negligible). One EX2 total.
        const float T0 = ex2(-(prefix + c0));
        const float T1 = T0 * u[1];
        const float T2 = T1 * u[2];
        const float T3 = T2 * u[3];
        const float w0 = T0 * (1.0f - u[0]);
        const float w1 = T1 * (1.0f - u[1]);
        const float w2 = T2 * (1.0f - u[2]);
        const float w3 = T3 * (1.0f - u[3]);

        // sample0=(ca.x,ca.y,ca.z) sample1=(ca.w,cb.x,cb.y)
        // sample2=(cb.z,cb.w,cc.x) sample3=(cc.y,cc.z,cc.w)
        r = w0 * ca.x + w1 * ca.w + w2 * cb.z + w3 * cc.y;
        g = w0 * ca.y + w1 * cb.x + w2 * cb.w + w3 * cc.z;
        b = w0 * ca.z + w1 * cb.y + w2 * cc.x + w3 * cc.w;
    }

    // Warp reduction over lanes (samples).
#pragma unroll
    for (int off = 16; off > 0; off >>= 1) {
        r += __shfl_xor_sync(0xffffffffu, r, off);
        g += __shfl_xor_sync(0xffffffffu, g, off);
        b += __shfl_xor_sync(0xffffffffu, b, off);
    }

    if (lane == 0) {
        out[ray * 3 + 0] = r;
        out[ray * 3 + 1] = g;
        out[ray * 3 + 2] = b;
    }
}

extern "C" void kernel_launch(void* const* d_in, const int* in_sizes, int n_in,
                              void* d_out, int out_size)
{
    // Identify buffers defensively by size. color is [N,128,3] -> uniquely 3x
    // larger than sdf/depth ([N,128] each).
    int ic = 0;
    for (int i = 1; i < n_in; ++i)
        if (in_sizes[i] > in_sizes[ic]) ic = i;

    int ia, ib;  // the two equal-size buffers, in index order
    if (ic == 0)      { ia = 1; ib = 2; }
    else if (ic == 1) { ia = 0; ib = 2; }
    else              { ia = 0; ib = 1; }

    int is, id;  // sdf index, depth index
    if (ic == 0) {
        // color first => name-sorted metadata (color, depth_values, sdf)
        id = ia; is = ib;
    } else {
        // insertion order (sdf, color, depth_values)
        is = ia; id = ib;
    }

    const float* sdf   = (const float*)d_in[is];
    const float* color = (const float*)d_in[ic];
    const float* depth = (const float*)d_in[id];
    float* out = (float*)d_out;

    const int N = out_size / 3;                   // 65536 rays
    const int threads = 256;                      // 8 warps = 8 rays / block
    const int blocks  = (N * 32 + threads - 1) / threads;
    volume_sdf_render_kernel<<<blocks, threads>>>(sdf, color, depth, out, N);
}